// round 13
// baseline (speedup 1.0000x reference)
#include <cuda_runtime.h>
#include <cuda_fp16.h>
#include <cstdint>

#define LOG2E 1.4426950408889634f
#define C1 (0.17677669529663687f * LOG2E)   // sm_scale * log2(e)

// smem layout (bytes) — padded layout
#define OFF_MS 0                      // mask * log2e, 256 f32 (1024 B)
#define OFF_KH 1024                   // K hi fp16 [256][32], row stride 80 B
#define OFF_KL (OFF_KH + 256*80)      // K lo
#define OFF_VH (OFF_KL + 256*80)      // Vt hi fp16 [32][256], row stride 528 B
#define OFF_VL (OFF_VH + 32*528)      // Vt lo
#define SMEM_TOTAL (OFF_VL + 32*528)  // 75776 B

__device__ __forceinline__ float ex2f(float x) {
    float y; asm("ex2.approx.ftz.f32 %0, %1;" : "=f"(y) : "f"(x)); return y;
}
__device__ __forceinline__ uint32_t packh2(float a, float b) {
    __half2 t = __floats2half2_rn(a, b);   // low half = a
    return *(uint32_t*)&t;
}
__device__ __forceinline__ void splith2(float2 x, uint32_t& hi, uint32_t& lo) {
    __half2 hv = __floats2half2_rn(x.x, x.y);
    float2 hf = __half22float2(hv);
    hi = *(uint32_t*)&hv;
    lo = packh2(x.x - hf.x, x.y - hf.y);
}
__device__ __forceinline__ void mma16816(float* d, const uint32_t* a,
                                         uint32_t b0, uint32_t b1) {
    asm volatile(
        "mma.sync.aligned.m16n8k16.row.col.f32.f16.f16.f32 "
        "{%0,%1,%2,%3}, {%4,%5,%6,%7}, {%8,%9}, {%0,%1,%2,%3};"
        : "+f"(d[0]), "+f"(d[1]), "+f"(d[2]), "+f"(d[3])
        : "r"(a[0]), "r"(a[1]), "r"(a[2]), "r"(a[3]), "r"(b0), "r"(b1));
}

__global__ __launch_bounds__(128, 3)
void TFA_88089779241014_kernel(const float* __restrict__ q,
                               const float* __restrict__ k,
                               const float* __restrict__ v,
                               const float* __restrict__ mask,
                               const float* __restrict__ tri,
                               float* __restrict__ out) {
    extern __shared__ char smem[];

    const int tid  = threadIdx.x;
    const int lane = tid & 31;
    const int wid  = tid >> 5;          // 0..3
    const int g    = lane >> 2;
    const int c    = (lane & 3) * 2;
    const int tg   = lane & 3;

    const int head = blockIdx.x;        // n*4 + h : one CTA per full head
    const int n    = head >> 2;
    const int h    = head & 3;

    const float* kb = k + (size_t)head * 8192;
    const float* vb = v + (size_t)head * 8192;
    const float* mb = mask + (size_t)n * 256;

    // ---- stage K as fp16 hi/lo, [t][d] rows, 80B stride ----
    for (int i = tid; i < 4096; i += 128) {
        int t = i >> 4, c2 = (i & 15) << 1;
        float2 x = *(const float2*)(kb + t * 32 + c2);
        uint32_t hi, lo; splith2(x, hi, lo);
        *(uint32_t*)(smem + OFF_KH + t * 80 + c2 * 2) = hi;
        *(uint32_t*)(smem + OFF_KL + t * 80 + c2 * 2) = lo;
    }
    // ---- stage V transposed: Vt[d][t] fp16 hi/lo, 528B stride ----
    for (int i = tid; i < 2048; i += 128) {
        float4 x = ((const float4*)vb)[i];
        int t = i >> 3, d4 = (i & 7) << 2;
        float e[4] = {x.x, x.y, x.z, x.w};
        #pragma unroll
        for (int j = 0; j < 4; j++) {
            int d = d4 + j;
            __half hv = __float2half_rn(e[j]);
            __half lv = __float2half_rn(e[j] - __half2float(hv));
            *(__half*)(smem + OFF_VH + d * 528 + t * 2) = hv;
            *(__half*)(smem + OFF_VL + d * 528 + t * 2) = lv;
        }
    }
    for (int i = tid; i < 256; i += 128)
        *(float*)(smem + OFF_MS + i * 4) = mb[i] * LOG2E;

    // ---- Q fragments: warp owns 64 rows = four 16-row A-tiles (fp16 hi only) ----
    const int rowbase = wid * 64;
    const float* qrow = q + (size_t)head * 8192 + (size_t)rowbase * 32;
    uint32_t qh[4][2][4];
    #pragma unroll
    for (int m = 0; m < 4; m++) {
        const float* qm = qrow + m * 16 * 32;
        #pragma unroll
        for (int s = 0; s < 2; s++) {
            int k0 = s * 16;
            float2 a0 = *(const float2*)(qm + (g)     * 32 + k0 + c);
            float2 a1 = *(const float2*)(qm + (g + 8) * 32 + k0 + c);
            float2 a2 = *(const float2*)(qm + (g)     * 32 + k0 + 8 + c);
            float2 a3 = *(const float2*)(qm + (g + 8) * 32 + k0 + 8 + c);
            qh[m][s][0] = packh2(a0.x, a0.y);
            qh[m][s][1] = packh2(a1.x, a1.y);
            qh[m][s][2] = packh2(a2.x, a2.y);
            qh[m][s][3] = packh2(a3.x, a3.y);
        }
    }

    const float* trow = tri + (size_t)h * 65536 + (size_t)(rowbase + g) * 256;

    __syncthreads();

    float acc[4][4][4];                // [m][dn][frag]
    #pragma unroll
    for (int m = 0; m < 4; m++)
        #pragma unroll
        for (int dn = 0; dn < 4; dn++)
            #pragma unroll
            for (int j = 0; j < 4; j++) acc[m][dn][j] = 0.f;
    float sg[4] = {0.f, 0.f, 0.f, 0.f};
    float sh[4] = {0.f, 0.f, 0.f, 0.f};

    // ================= main loop over 16-key tiles =================
    #pragma unroll 1
    for (int kt = 0; kt < 16; kt++) {
        const int n0 = kt * 16;

        // ---- K fragment loads (scalar LDS, conflict-free; shared by all 4 m-tiles) ----
        const char* kA = smem + (n0 + g)     * 80 + tg * 4;
        const char* kB = smem + (n0 + 8 + g) * 80 + tg * 4;
        uint32_t bAh[4], bAl[4], bBh[4], bBl[4];
        #pragma unroll
        for (int s = 0; s < 2; s++) {
            bAh[2*s]   = *(const uint32_t*)(kA + OFF_KH + s * 32);
            bAh[2*s+1] = *(const uint32_t*)(kA + OFF_KH + s * 32 + 16);
            bAl[2*s]   = *(const uint32_t*)(kA + OFF_KL + s * 32);
            bAl[2*s+1] = *(const uint32_t*)(kA + OFF_KL + s * 32 + 16);
            bBh[2*s]   = *(const uint32_t*)(kB + OFF_KH + s * 32);
            bBh[2*s+1] = *(const uint32_t*)(kB + OFF_KH + s * 32 + 16);
            bBl[2*s]   = *(const uint32_t*)(kB + OFF_KL + s * 32);
            bBl[2*s+1] = *(const uint32_t*)(kB + OFF_KL + s * 32 + 16);
        }

        // ---- QK^T: fp16 2-product, 4 m-tiles on the same B-frags (32 MMAs) ----
        float dA[4][4], dB[4][4];
        #pragma unroll
        for (int m = 0; m < 4; m++)
            #pragma unroll
            for (int j = 0; j < 4; j++) { dA[m][j] = 0.f; dB[m][j] = 0.f; }
        #pragma unroll
        for (int m = 0; m < 4; m++) {
            mma16816(dA[m], qh[m][0], bAh[0], bAh[1]);
            mma16816(dB[m], qh[m][0], bBh[0], bBh[1]);
        }
        #pragma unroll
        for (int m = 0; m < 4; m++) {
            mma16816(dA[m], qh[m][1], bAh[2], bAh[3]);
            mma16816(dB[m], qh[m][1], bBh[2], bBh[3]);
        }
        #pragma unroll
        for (int m = 0; m < 4; m++) {
            mma16816(dA[m], qh[m][0], bAl[0], bAl[1]);
            mma16816(dB[m], qh[m][0], bBl[0], bBl[1]);
        }
        #pragma unroll
        for (int m = 0; m < 4; m++) {
            mma16816(dA[m], qh[m][1], bAl[2], bAl[3]);
            mma16816(dB[m], qh[m][1], bBl[2], bBl[3]);
        }

        // ---- bias + exp2 per m-tile (no max subtraction; fp32-safe) ----
        float2 msA = *(const float2*)(smem + OFF_MS + (n0 + c) * 4);
        float2 msB = *(const float2*)(smem + OFF_MS + (n0 + 8 + c) * 4);
        uint32_t ph[4][4];
        #pragma unroll
        for (int m = 0; m < 4; m++) {
            const float* tm = trow + m * 16 * 256;
            float2 tA = *(const float2*)(tm            + n0 + c);
            float2 tB = *(const float2*)(tm            + n0 + 8 + c);
            float2 tC = *(const float2*)(tm + 8 * 256  + n0 + c);
            float2 tD = *(const float2*)(tm + 8 * 256  + n0 + 8 + c);
            float e00 = ex2f(fmaf(dA[m][0], C1, fmaf(tA.x, LOG2E, msA.x)));
            float e01 = ex2f(fmaf(dA[m][1], C1, fmaf(tA.y, LOG2E, msA.y)));
            float e02 = ex2f(fmaf(dA[m][2], C1, fmaf(tC.x, LOG2E, msA.x)));
            float e03 = ex2f(fmaf(dA[m][3], C1, fmaf(tC.y, LOG2E, msA.y)));
            float e10 = ex2f(fmaf(dB[m][0], C1, fmaf(tB.x, LOG2E, msB.x)));
            float e11 = ex2f(fmaf(dB[m][1], C1, fmaf(tB.y, LOG2E, msB.y)));
            float e12 = ex2f(fmaf(dB[m][2], C1, fmaf(tD.x, LOG2E, msB.x)));
            float e13 = ex2f(fmaf(dB[m][3], C1, fmaf(tD.y, LOG2E, msB.y)));
            sg[m] += (e00 + e01) + (e10 + e11);
            sh[m] += (e02 + e03) + (e12 + e13);
            ph[m][0] = packh2(e00, e01);
            ph[m][1] = packh2(e02, e03);
            ph[m][2] = packh2(e10, e11);
            ph[m][3] = packh2(e12, e13);
        }

        // ---- PV: fp16 2-product, 4 m-tiles on the same V-frags (32 MMAs) ----
        #pragma unroll
        for (int dn = 0; dn < 4; dn++) {
            const char* vrow = smem + (dn * 8 + g) * 528 + n0 * 2 + tg * 4;
            uint32_t vh0 = *(const uint32_t*)(vrow + OFF_VH);
            uint32_t vh1 = *(const uint32_t*)(vrow + OFF_VH + 16);
            uint32_t vl0 = *(const uint32_t*)(vrow + OFF_VL);
            uint32_t vl1 = *(const uint32_t*)(vrow + OFF_VL + 16);
            #pragma unroll
            for (int m = 0; m < 4; m++) {
                mma16816(acc[m][dn], ph[m], vh0, vh1);
                mma16816(acc[m][dn], ph[m], vl0, vl1);
            }
        }
    }

    // ---- row-sum reduce within quad ----
    #pragma unroll
    for (int m = 0; m < 4; m++) {
        sg[m] += __shfl_xor_sync(0xffffffffu, sg[m], 1);
        sg[m] += __shfl_xor_sync(0xffffffffu, sg[m], 2);
        sh[m] += __shfl_xor_sync(0xffffffffu, sh[m], 1);
        sh[m] += __shfl_xor_sync(0xffffffffu, sh[m], 2);
    }

    // ---- store (rows rowbase + m*16 + g + {0,8}) ----
    float* orow = out + (size_t)head * 8192 + (size_t)rowbase * 32;
    #pragma unroll
    for (int m = 0; m < 4; m++) {
        const float rg = 1.f / sg[m];
        const float rh = 1.f / sh[m];
        float* om = orow + m * 16 * 32;
        #pragma unroll
        for (int dn = 0; dn < 4; dn++) {
            float2 w;
            w.x = acc[m][dn][0] * rg; w.y = acc[m][dn][1] * rg;
            *(float2*)(om + (g)     * 32 + dn * 8 + c) = w;
            w.x = acc[m][dn][2] * rh; w.y = acc[m][dn][3] * rh;
            *(float2*)(om + (g + 8) * 32 + dn * 8 + c) = w;
        }
    }
}

extern "C" void kernel_launch(void* const* d_in, const int* in_sizes, int n_in,
                              void* d_out, int out_size) {
    const float* q    = (const float*)d_in[0];
    const float* k    = (const float*)d_in[1];
    const float* v    = (const float*)d_in[2];
    const float* mask = (const float*)d_in[3];
    const float* tri  = (const float*)d_in[4];
    float* out = (float*)d_out;

    cudaFuncSetAttribute(TFA_88089779241014_kernel,
                         cudaFuncAttributeMaxDynamicSharedMemorySize, SMEM_TOTAL);
    // one CTA per head: 1024 CTAs, 128 threads (4 warps x 64 query rows)
    TFA_88089779241014_kernel<<<1024, 128, SMEM_TOTAL>>>(q, k, v, mask, tri, out);
}

// round 14
// speedup vs baseline: 1.3050x; 1.3050x over previous
#include <cuda_runtime.h>
#include <cuda_fp16.h>
#include <cstdint>

#define LOG2E 1.4426950408889634f
#define C1 (0.17677669529663687f * LOG2E)   // sm_scale * log2(e)

// smem layout (bytes) — padded layout
#define OFF_MS 0                      // mask * log2e, 256 f32 (1024 B)
#define OFF_KH 1024                   // K hi fp16 [256][32], row stride 80 B
#define OFF_KL (OFF_KH + 256*80)      // K lo
#define OFF_VH (OFF_KL + 256*80)      // Vt hi fp16 [32][256], row stride 528 B
#define OFF_VL (OFF_VH + 32*528)      // Vt lo
#define SMEM_TOTAL (OFF_VL + 32*528)  // 75776 B

// fragment-ordered triangle bias (x LOG2E): [h][warp][kt][grp][lane] float4
// 4 * 8 * 16 * 4 * 32 = 65536 float4 = 1 MB
__device__ float4 g_triw[65536];

__device__ __forceinline__ float ex2f(float x) {
    float y; asm("ex2.approx.ftz.f32 %0, %1;" : "=f"(y) : "f"(x)); return y;
}
__device__ __forceinline__ uint32_t packh2(float a, float b) {
    __half2 t = __floats2half2_rn(a, b);   // low half = a
    return *(uint32_t*)&t;
}
__device__ __forceinline__ void splith2(float2 x, uint32_t& hi, uint32_t& lo) {
    __half2 hv = __floats2half2_rn(x.x, x.y);
    float2 hf = __half22float2(hv);
    hi = *(uint32_t*)&hv;
    lo = packh2(x.x - hf.x, x.y - hf.y);
}
__device__ __forceinline__ void mma16816(float* d, const uint32_t* a,
                                         uint32_t b0, uint32_t b1) {
    asm volatile(
        "mma.sync.aligned.m16n8k16.row.col.f32.f16.f16.f32 "
        "{%0,%1,%2,%3}, {%4,%5,%6,%7}, {%8,%9}, {%0,%1,%2,%3};"
        : "+f"(d[0]), "+f"(d[1]), "+f"(d[2]), "+f"(d[3])
        : "r"(a[0]), "r"(a[1]), "r"(a[2]), "r"(a[3]), "r"(b0), "r"(b1));
}

// ---- pre-pass: gather triangle_bias into fragment order, scaled by LOG2E ----
__global__ void tri_prep_kernel(const float* __restrict__ tri) {
    const int o    = blockIdx.x * 256 + threadIdx.x;   // 0..65535
    const int lane = o & 31;
    const int grp  = (o >> 5) & 3;
    const int kt   = (o >> 7) & 15;
    const int w    = (o >> 11) & 7;
    const int h    = o >> 14;
    const int g    = lane >> 2;
    const int c    = (lane & 3) * 2;
    const int row  = w * 32 + (grp & 1) * 8 + ((grp >> 1) & 1) * 16 + g;
    const float* src = tri + (size_t)h * 65536 + (size_t)row * 256 + kt * 16;
    float4 v;
    v.x = src[c]     * LOG2E;
    v.y = src[c + 1] * LOG2E;
    v.z = src[c + 8] * LOG2E;
    v.w = src[c + 9] * LOG2E;
    g_triw[o] = v;
}

__global__ __launch_bounds__(256, 2)
void TFA_88089779241014_kernel(const float* __restrict__ q,
                               const float* __restrict__ k,
                               const float* __restrict__ v,
                               const float* __restrict__ mask,
                               float* __restrict__ out) {
    extern __shared__ char smem[];

    const int tid  = threadIdx.x;
    const int lane = tid & 31;
    const int wid  = tid >> 5;
    const int g    = lane >> 2;
    const int c    = (lane & 3) * 2;
    const int tg   = lane & 3;

    const int head = blockIdx.x;        // n*4 + h : one CTA per full head
    const int n    = head >> 2;
    const int h    = head & 3;

    const float* kb = k + (size_t)head * 8192;
    const float* vb = v + (size_t)head * 8192;
    const float* mb = mask + (size_t)n * 256;

    // ---- stage K as fp16 hi/lo, [t][d] rows, 80B stride ----
    for (int i = tid; i < 4096; i += 256) {
        int t = i >> 4, c2 = (i & 15) << 1;
        float2 x = *(const float2*)(kb + t * 32 + c2);
        uint32_t hi, lo; splith2(x, hi, lo);
        *(uint32_t*)(smem + OFF_KH + t * 80 + c2 * 2) = hi;
        *(uint32_t*)(smem + OFF_KL + t * 80 + c2 * 2) = lo;
    }
    // ---- stage V transposed: Vt[d][t] fp16 hi/lo, 528B stride ----
    for (int i = tid; i < 2048; i += 256) {
        float4 x = ((const float4*)vb)[i];
        int t = i >> 3, d4 = (i & 7) << 2;
        float e[4] = {x.x, x.y, x.z, x.w};
        #pragma unroll
        for (int j = 0; j < 4; j++) {
            int d = d4 + j;
            __half hv = __float2half_rn(e[j]);
            __half lv = __float2half_rn(e[j] - __half2float(hv));
            *(__half*)(smem + OFF_VH + d * 528 + t * 2) = hv;
            *(__half*)(smem + OFF_VL + d * 528 + t * 2) = lv;
        }
    }
    for (int i = tid; i < 256; i += 256)
        *(float*)(smem + OFF_MS + i * 4) = mb[i] * LOG2E;

    // ---- Q fragments: warp owns 32 rows = two 16-row A-tiles (fp16 hi only) ----
    const int rowbase = wid * 32;
    const float* qrow = q + (size_t)head * 8192 + (size_t)rowbase * 32;
    uint32_t qh0[2][4], qh1[2][4];
    #pragma unroll
    for (int s = 0; s < 2; s++) {
        int k0 = s * 16;
        #pragma unroll
        for (int m = 0; m < 2; m++) {
            const float* qm = qrow + m * 16 * 32;
            float2 a0 = *(const float2*)(qm + (g)     * 32 + k0 + c);
            float2 a1 = *(const float2*)(qm + (g + 8) * 32 + k0 + c);
            float2 a2 = *(const float2*)(qm + (g)     * 32 + k0 + 8 + c);
            float2 a3 = *(const float2*)(qm + (g + 8) * 32 + k0 + 8 + c);
            uint32_t* dst = m ? qh1[s] : qh0[s];
            dst[0] = packh2(a0.x, a0.y);
            dst[1] = packh2(a1.x, a1.y);
            dst[2] = packh2(a2.x, a2.y);
            dst[3] = packh2(a3.x, a3.y);
        }
    }

    // fragment-ordered tri base for this (h, warp): + kt*128 + grp*32 + lane
    const float4* tb4 = g_triw + ((size_t)(h * 8 + wid) * 16) * 128 + lane;

    __syncthreads();

    float acc0[4][4], acc1[4][4];
    #pragma unroll
    for (int dn = 0; dn < 4; dn++)
        #pragma unroll
        for (int j = 0; j < 4; j++) { acc0[dn][j] = 0.f; acc1[dn][j] = 0.f; }
    float s0g = 0.f, s0h = 0.f, s1g = 0.f, s1h = 0.f;

    // ================= main loop over 16-key tiles =================
    #pragma unroll 1
    for (int kt = 0; kt < 16; kt++) {
        const int n0 = kt * 16;

        // ---- tri bias: 4 coalesced LDG.128 (fragment-ordered, L2-hot) ----
        const float4* tb = tb4 + kt * 128;
        float4 t0 = tb[0];      // m0 rows g    : (n0+c, n0+c+1, n0+8+c, n0+8+c+1)
        float4 t1 = tb[32];     // m0 rows g+8
        float4 t2 = tb[64];     // m1 rows g+16
        float4 t3 = tb[96];     // m1 rows g+24

        // ---- K fragment loads (scalar LDS, conflict-free; shared by both m-tiles) ----
        const char* kA = smem + (n0 + g)     * 80 + tg * 4;
        const char* kB = smem + (n0 + 8 + g) * 80 + tg * 4;
        uint32_t bAh[4], bAl[4], bBh[4], bBl[4];
        #pragma unroll
        for (int s = 0; s < 2; s++) {
            bAh[2*s]   = *(const uint32_t*)(kA + OFF_KH + s * 32);
            bAh[2*s+1] = *(const uint32_t*)(kA + OFF_KH + s * 32 + 16);
            bAl[2*s]   = *(const uint32_t*)(kA + OFF_KL + s * 32);
            bAl[2*s+1] = *(const uint32_t*)(kA + OFF_KL + s * 32 + 16);
            bBh[2*s]   = *(const uint32_t*)(kB + OFF_KH + s * 32);
            bBh[2*s+1] = *(const uint32_t*)(kB + OFF_KH + s * 32 + 16);
            bBl[2*s]   = *(const uint32_t*)(kB + OFF_KL + s * 32);
            bBl[2*s+1] = *(const uint32_t*)(kB + OFF_KL + s * 32 + 16);
        }

        // ---- QK^T: fp16 2-product, both m-tiles on the same B-frags (16 MMAs) ----
        float d00[4] = {0.f,0.f,0.f,0.f}, d01[4] = {0.f,0.f,0.f,0.f};
        float d10[4] = {0.f,0.f,0.f,0.f}, d11[4] = {0.f,0.f,0.f,0.f};
        mma16816(d00, qh0[0], bAh[0], bAh[1]);
        mma16816(d01, qh0[0], bBh[0], bBh[1]);
        mma16816(d10, qh1[0], bAh[0], bAh[1]);
        mma16816(d11, qh1[0], bBh[0], bBh[1]);
        mma16816(d00, qh0[1], bAh[2], bAh[3]);
        mma16816(d01, qh0[1], bBh[2], bBh[3]);
        mma16816(d10, qh1[1], bAh[2], bAh[3]);
        mma16816(d11, qh1[1], bBh[2], bBh[3]);
        mma16816(d00, qh0[0], bAl[0], bAl[1]);
        mma16816(d01, qh0[0], bBl[0], bBl[1]);
        mma16816(d10, qh1[0], bAl[0], bAl[1]);
        mma16816(d11, qh1[0], bBl[0], bBl[1]);
        mma16816(d00, qh0[1], bAl[2], bAl[3]);
        mma16816(d01, qh0[1], bBl[2], bBl[3]);
        mma16816(d10, qh1[1], bAl[2], bAl[3]);
        mma16816(d11, qh1[1], bBl[2], bBl[3]);

        // ---- bias + exp2 (no max subtraction; fp32-safe) ----
        float2 msA = *(const float2*)(smem + OFF_MS + (n0 + c) * 4);
        float2 msB = *(const float2*)(smem + OFF_MS + (n0 + 8 + c) * 4);

        // m-tile 0
        float e00 = ex2f(fmaf(d00[0], C1, t0.x + msA.x));
        float e01 = ex2f(fmaf(d00[1], C1, t0.y + msA.y));
        float e02 = ex2f(fmaf(d00[2], C1, t1.x + msA.x));
        float e03 = ex2f(fmaf(d00[3], C1, t1.y + msA.y));
        float e10 = ex2f(fmaf(d01[0], C1, t0.z + msB.x));
        float e11 = ex2f(fmaf(d01[1], C1, t0.w + msB.y));
        float e12 = ex2f(fmaf(d01[2], C1, t1.z + msB.x));
        float e13 = ex2f(fmaf(d01[3], C1, t1.w + msB.y));
        s0g += (e00 + e01) + (e10 + e11);
        s0h += (e02 + e03) + (e12 + e13);
        uint32_t ph0[4];
        ph0[0] = packh2(e00, e01);
        ph0[1] = packh2(e02, e03);
        ph0[2] = packh2(e10, e11);
        ph0[3] = packh2(e12, e13);

        // m-tile 1
        e00 = ex2f(fmaf(d10[0], C1, t2.x + msA.x));
        e01 = ex2f(fmaf(d10[1], C1, t2.y + msA.y));
        e02 = ex2f(fmaf(d10[2], C1, t3.x + msA.x));
        e03 = ex2f(fmaf(d10[3], C1, t3.y + msA.y));
        e10 = ex2f(fmaf(d11[0], C1, t2.z + msB.x));
        e11 = ex2f(fmaf(d11[1], C1, t2.w + msB.y));
        e12 = ex2f(fmaf(d11[2], C1, t3.z + msB.x));
        e13 = ex2f(fmaf(d11[3], C1, t3.w + msB.y));
        s1g += (e00 + e01) + (e10 + e11);
        s1h += (e02 + e03) + (e12 + e13);
        uint32_t ph1[4];
        ph1[0] = packh2(e00, e01);
        ph1[1] = packh2(e02, e03);
        ph1[2] = packh2(e10, e11);
        ph1[3] = packh2(e12, e13);

        // ---- PV: fp16 2-product, both m-tiles on the same V-frags (16 MMAs) ----
        #pragma unroll
        for (int dn = 0; dn < 4; dn++) {
            const char* vrow = smem + (dn * 8 + g) * 528 + n0 * 2 + tg * 4;
            uint32_t vh0 = *(const uint32_t*)(vrow + OFF_VH);
            uint32_t vh1 = *(const uint32_t*)(vrow + OFF_VH + 16);
            uint32_t vl0 = *(const uint32_t*)(vrow + OFF_VL);
            uint32_t vl1 = *(const uint32_t*)(vrow + OFF_VL + 16);
            mma16816(acc0[dn], ph0, vh0, vh1);
            mma16816(acc1[dn], ph1, vh0, vh1);
            mma16816(acc0[dn], ph0, vl0, vl1);
            mma16816(acc1[dn], ph1, vl0, vl1);
        }
    }

    // ---- row-sum reduce within quad ----
    s0g += __shfl_xor_sync(0xffffffffu, s0g, 1);
    s0g += __shfl_xor_sync(0xffffffffu, s0g, 2);
    s0h += __shfl_xor_sync(0xffffffffu, s0h, 1);
    s0h += __shfl_xor_sync(0xffffffffu, s0h, 2);
    s1g += __shfl_xor_sync(0xffffffffu, s1g, 1);
    s1g += __shfl_xor_sync(0xffffffffu, s1g, 2);
    s1h += __shfl_xor_sync(0xffffffffu, s1h, 1);
    s1h += __shfl_xor_sync(0xffffffffu, s1h, 2);
    const float r0g = 1.f / s0g, r0h = 1.f / s0h;
    const float r1g = 1.f / s1g, r1h = 1.f / s1h;

    // ---- store (rows rowbase + g + {0,8,16,24}) ----
    float* orow = out + (size_t)head * 8192 + (size_t)rowbase * 32;
    #pragma unroll
    for (int dn = 0; dn < 4; dn++) {
        float2 w;
        w.x = acc0[dn][0] * r0g; w.y = acc0[dn][1] * r0g;
        *(float2*)(orow + (g)      * 32 + dn * 8 + c) = w;
        w.x = acc0[dn][2] * r0h; w.y = acc0[dn][3] * r0h;
        *(float2*)(orow + (g + 8)  * 32 + dn * 8 + c) = w;
        w.x = acc1[dn][0] * r1g; w.y = acc1[dn][1] * r1g;
        *(float2*)(orow + (g + 16) * 32 + dn * 8 + c) = w;
        w.x = acc1[dn][2] * r1h; w.y = acc1[dn][3] * r1h;
        *(float2*)(orow + (g + 24) * 32 + dn * 8 + c) = w;
    }
}

extern "C" void kernel_launch(void* const* d_in, const int* in_sizes, int n_in,
                              void* d_out, int out_size) {
    const float* q    = (const float*)d_in[0];
    const float* k    = (const float*)d_in[1];
    const float* v    = (const float*)d_in[2];
    const float* mask = (const float*)d_in[3];
    const float* tri  = (const float*)d_in[4];
    float* out = (float*)d_out;

    cudaFuncSetAttribute(TFA_88089779241014_kernel,
                         cudaFuncAttributeMaxDynamicSharedMemorySize, SMEM_TOTAL);

    // pre-pass: fragment-order the triangle bias (65536 float4 / 256 thr)
    tri_prep_kernel<<<256, 256>>>(tri);
    // one CTA per head: 1024 CTAs, 256 threads (8 warps x 32 query rows)
    TFA_88089779241014_kernel<<<1024, 256, SMEM_TOTAL>>>(q, k, v, mask, out);
}

// round 15
// speedup vs baseline: 1.4168x; 1.0857x over previous
#include <cuda_runtime.h>
#include <cuda_fp16.h>
#include <cstdint>

#define LOG2E 1.4426950408889634f
#define C1 (0.17677669529663687f * LOG2E)   // sm_scale * log2(e)

// smem layout (bytes) — fp16 hi-only, padded
#define OFF_MS 0                      // mask * log2e, 256 f32 (1024 B)
#define OFF_KH 1024                   // K fp16 [256][32], row stride 80 B
#define OFF_VH (OFF_KH + 256*80)      // Vt fp16 [32][256], row stride 528 B
#define SMEM_TOTAL (OFF_VH + 32*528)  // 38400 B

// fragment-ordered triangle bias (x LOG2E): [h][warp][kt][grp][lane] float4
__device__ float4 g_triw[65536];      // 1 MB

__device__ __forceinline__ float ex2f(float x) {
    float y; asm("ex2.approx.ftz.f32 %0, %1;" : "=f"(y) : "f"(x)); return y;
}
__device__ __forceinline__ uint32_t packh2(float a, float b) {
    __half2 t = __floats2half2_rn(a, b);   // low half = a
    return *(uint32_t*)&t;
}
__device__ __forceinline__ void mma16816(float* d, const uint32_t* a,
                                         uint32_t b0, uint32_t b1) {
    asm volatile(
        "mma.sync.aligned.m16n8k16.row.col.f32.f16.f16.f32 "
        "{%0,%1,%2,%3}, {%4,%5,%6,%7}, {%8,%9}, {%0,%1,%2,%3};"
        : "+f"(d[0]), "+f"(d[1]), "+f"(d[2]), "+f"(d[3])
        : "r"(a[0]), "r"(a[1]), "r"(a[2]), "r"(a[3]), "r"(b0), "r"(b1));
}

// ---- pre-pass: gather triangle_bias into fragment order, scaled by LOG2E ----
__global__ void tri_prep_kernel(const float* __restrict__ tri) {
    const int o    = blockIdx.x * 256 + threadIdx.x;   // 0..65535
    const int lane = o & 31;
    const int grp  = (o >> 5) & 3;
    const int kt   = (o >> 7) & 15;
    const int w    = (o >> 11) & 7;
    const int h    = o >> 14;
    const int g    = lane >> 2;
    const int c    = (lane & 3) * 2;
    const int row  = w * 32 + (grp & 1) * 8 + ((grp >> 1) & 1) * 16 + g;
    const float* src = tri + (size_t)h * 65536 + (size_t)row * 256 + kt * 16;
    float4 v;
    v.x = src[c]     * LOG2E;
    v.y = src[c + 1] * LOG2E;
    v.z = src[c + 8] * LOG2E;
    v.w = src[c + 9] * LOG2E;
    g_triw[o] = v;
}

__global__ __launch_bounds__(256, 2)
void TFA_88089779241014_kernel(const float* __restrict__ q,
                               const float* __restrict__ k,
                               const float* __restrict__ v,
                               const float* __restrict__ mask,
                               float* __restrict__ out) {
    extern __shared__ char smem[];

    const int tid  = threadIdx.x;
    const int lane = tid & 31;
    const int wid  = tid >> 5;
    const int g    = lane >> 2;
    const int c    = (lane & 3) * 2;
    const int tg   = lane & 3;

    const int head = blockIdx.x;        // n*4 + h : one CTA per full head
    const int n    = head >> 2;
    const int h    = head & 3;

    const float* kb = k + (size_t)head * 8192;
    const float* vb = v + (size_t)head * 8192;
    const float* mb = mask + (size_t)n * 256;

    // ---- stage K as fp16, [t][d] rows, 80B stride ----
    for (int i = tid; i < 4096; i += 256) {
        int t = i >> 4, c2 = (i & 15) << 1;
        float2 x = *(const float2*)(kb + t * 32 + c2);
        *(uint32_t*)(smem + OFF_KH + t * 80 + c2 * 2) = packh2(x.x, x.y);
    }
    // ---- stage V transposed: Vt[d][t] fp16, 528B stride ----
    for (int i = tid; i < 2048; i += 256) {
        float4 x = ((const float4*)vb)[i];
        int t = i >> 3, d4 = (i & 7) << 2;
        float e[4] = {x.x, x.y, x.z, x.w};
        #pragma unroll
        for (int j = 0; j < 4; j++) {
            int d = d4 + j;
            *(__half*)(smem + OFF_VH + d * 528 + t * 2) = __float2half_rn(e[j]);
        }
    }
    for (int i = tid; i < 256; i += 256)
        *(float*)(smem + OFF_MS + i * 4) = mb[i] * LOG2E;

    // ---- Q fragments: warp owns 32 rows = two 16-row A-tiles (fp16) ----
    const int rowbase = wid * 32;
    const float* qrow = q + (size_t)head * 8192 + (size_t)rowbase * 32;
    uint32_t qh0[2][4], qh1[2][4];
    #pragma unroll
    for (int s = 0; s < 2; s++) {
        int k0 = s * 16;
        #pragma unroll
        for (int m = 0; m < 2; m++) {
            const float* qm = qrow + m * 16 * 32;
            float2 a0 = *(const float2*)(qm + (g)     * 32 + k0 + c);
            float2 a1 = *(const float2*)(qm + (g + 8) * 32 + k0 + c);
            float2 a2 = *(const float2*)(qm + (g)     * 32 + k0 + 8 + c);
            float2 a3 = *(const float2*)(qm + (g + 8) * 32 + k0 + 8 + c);
            uint32_t* dst = m ? qh1[s] : qh0[s];
            dst[0] = packh2(a0.x, a0.y);
            dst[1] = packh2(a1.x, a1.y);
            dst[2] = packh2(a2.x, a2.y);
            dst[3] = packh2(a3.x, a3.y);
        }
    }

    // fragment-ordered tri base for this (h, warp): + kt*128 + grp*32 + lane
    const float4* tb4 = g_triw + ((size_t)(h * 8 + wid) * 16) * 128 + lane;

    __syncthreads();

    float acc0[4][4], acc1[4][4];
    #pragma unroll
    for (int dn = 0; dn < 4; dn++)
        #pragma unroll
        for (int j = 0; j < 4; j++) { acc0[dn][j] = 0.f; acc1[dn][j] = 0.f; }
    float s0g = 0.f, s0h = 0.f, s1g = 0.f, s1h = 0.f;

    // ================= main loop over 16-key tiles =================
    #pragma unroll 1
    for (int kt = 0; kt < 16; kt++) {
        const int n0 = kt * 16;

        // ---- tri bias: 4 coalesced LDG.128 (fragment-ordered, L2-hot) ----
        const float4* tb = tb4 + kt * 128;
        float4 t0 = tb[0];      // m0 rows g    : (n0+c, +1, n0+8+c, +1)
        float4 t1 = tb[32];     // m0 rows g+8
        float4 t2 = tb[64];     // m1 rows g+16
        float4 t3 = tb[96];     // m1 rows g+24

        // ---- K fragment loads (8 scalar LDS, conflict-free; shared by m-tiles) ----
        const char* kA = smem + OFF_KH + (n0 + g)     * 80 + tg * 4;
        const char* kB = smem + OFF_KH + (n0 + 8 + g) * 80 + tg * 4;
        uint32_t bAh[4], bBh[4];
        #pragma unroll
        for (int s = 0; s < 2; s++) {
            bAh[2*s]   = *(const uint32_t*)(kA + s * 32);
            bAh[2*s+1] = *(const uint32_t*)(kA + s * 32 + 16);
            bBh[2*s]   = *(const uint32_t*)(kB + s * 32);
            bBh[2*s+1] = *(const uint32_t*)(kB + s * 32 + 16);
        }

        // ---- QK^T: fp16 single product, both m-tiles (8 MMAs) ----
        float d00[4] = {0.f,0.f,0.f,0.f}, d01[4] = {0.f,0.f,0.f,0.f};
        float d10[4] = {0.f,0.f,0.f,0.f}, d11[4] = {0.f,0.f,0.f,0.f};
        mma16816(d00, qh0[0], bAh[0], bAh[1]);
        mma16816(d01, qh0[0], bBh[0], bBh[1]);
        mma16816(d10, qh1[0], bAh[0], bAh[1]);
        mma16816(d11, qh1[0], bBh[0], bBh[1]);
        mma16816(d00, qh0[1], bAh[2], bAh[3]);
        mma16816(d01, qh0[1], bBh[2], bBh[3]);
        mma16816(d10, qh1[1], bAh[2], bAh[3]);
        mma16816(d11, qh1[1], bBh[2], bBh[3]);

        // ---- bias + exp2 (no max subtraction; fp32-safe) ----
        float2 msA = *(const float2*)(smem + OFF_MS + (n0 + c) * 4);
        float2 msB = *(const float2*)(smem + OFF_MS + (n0 + 8 + c) * 4);

        // m-tile 0
        float e00 = ex2f(fmaf(d00[0], C1, t0.x + msA.x));
        float e01 = ex2f(fmaf(d00[1], C1, t0.y + msA.y));
        float e02 = ex2f(fmaf(d00[2], C1, t1.x + msA.x));
        float e03 = ex2f(fmaf(d00[3], C1, t1.y + msA.y));
        float e10 = ex2f(fmaf(d01[0], C1, t0.z + msB.x));
        float e11 = ex2f(fmaf(d01[1], C1, t0.w + msB.y));
        float e12 = ex2f(fmaf(d01[2], C1, t1.z + msB.x));
        float e13 = ex2f(fmaf(d01[3], C1, t1.w + msB.y));
        s0g += (e00 + e01) + (e10 + e11);
        s0h += (e02 + e03) + (e12 + e13);
        uint32_t ph0[4];
        ph0[0] = packh2(e00, e01);
        ph0[1] = packh2(e02, e03);
        ph0[2] = packh2(e10, e11);
        ph0[3] = packh2(e12, e13);

        // m-tile 1
        e00 = ex2f(fmaf(d10[0], C1, t2.x + msA.x));
        e01 = ex2f(fmaf(d10[1], C1, t2.y + msA.y));
        e02 = ex2f(fmaf(d10[2], C1, t3.x + msA.x));
        e03 = ex2f(fmaf(d10[3], C1, t3.y + msA.y));
        e10 = ex2f(fmaf(d11[0], C1, t2.z + msB.x));
        e11 = ex2f(fmaf(d11[1], C1, t2.w + msB.y));
        e12 = ex2f(fmaf(d11[2], C1, t3.z + msB.x));
        e13 = ex2f(fmaf(d11[3], C1, t3.w + msB.y));
        s1g += (e00 + e01) + (e10 + e11);
        s1h += (e02 + e03) + (e12 + e13);
        uint32_t ph1[4];
        ph1[0] = packh2(e00, e01);
        ph1[1] = packh2(e02, e03);
        ph1[2] = packh2(e10, e11);
        ph1[3] = packh2(e12, e13);

        // ---- PV: fp16 single product, both m-tiles (8 LDS + 8 MMAs) ----
        #pragma unroll
        for (int dn = 0; dn < 4; dn++) {
            const char* vrow = smem + OFF_VH + (dn * 8 + g) * 528 + n0 * 2 + tg * 4;
            uint32_t vh0 = *(const uint32_t*)(vrow);
            uint32_t vh1 = *(const uint32_t*)(vrow + 16);
            mma16816(acc0[dn], ph0, vh0, vh1);
            mma16816(acc1[dn], ph1, vh0, vh1);
        }
    }

    // ---- row-sum reduce within quad ----
    s0g += __shfl_xor_sync(0xffffffffu, s0g, 1);
    s0g += __shfl_xor_sync(0xffffffffu, s0g, 2);
    s0h += __shfl_xor_sync(0xffffffffu, s0h, 1);
    s0h += __shfl_xor_sync(0xffffffffu, s0h, 2);
    s1g += __shfl_xor_sync(0xffffffffu, s1g, 1);
    s1g += __shfl_xor_sync(0xffffffffu, s1g, 2);
    s1h += __shfl_xor_sync(0xffffffffu, s1h, 1);
    s1h += __shfl_xor_sync(0xffffffffu, s1h, 2);
    const float r0g = 1.f / s0g, r0h = 1.f / s0h;
    const float r1g = 1.f / s1g, r1h = 1.f / s1h;

    // ---- store (rows rowbase + g + {0,8,16,24}) ----
    float* orow = out + (size_t)head * 8192 + (size_t)rowbase * 32;
    #pragma unroll
    for (int dn = 0; dn < 4; dn++) {
        float2 w;
        w.x = acc0[dn][0] * r0g; w.y = acc0[dn][1] * r0g;
        *(float2*)(orow + (g)      * 32 + dn * 8 + c) = w;
        w.x = acc0[dn][2] * r0h; w.y = acc0[dn][3] * r0h;
        *(float2*)(orow + (g + 8)  * 32 + dn * 8 + c) = w;
        w.x = acc1[dn][0] * r1g; w.y = acc1[dn][1] * r1g;
        *(float2*)(orow + (g + 16) * 32 + dn * 8 + c) = w;
        w.x = acc1[dn][2] * r1h; w.y = acc1[dn][3] * r1h;
        *(float2*)(orow + (g + 24) * 32 + dn * 8 + c) = w;
    }
}

extern "C" void kernel_launch(void* const* d_in, const int* in_sizes, int n_in,
                              void* d_out, int out_size) {
    const float* q    = (const float*)d_in[0];
    const float* k    = (const float*)d_in[1];
    const float* v    = (const float*)d_in[2];
    const float* mask = (const float*)d_in[3];
    const float* tri  = (const float*)d_in[4];
    float* out = (float*)d_out;

    cudaFuncSetAttribute(TFA_88089779241014_kernel,
                         cudaFuncAttributeMaxDynamicSharedMemorySize, SMEM_TOTAL);

    // pre-pass: fragment-order the triangle bias (65536 float4 / 256 thr)
    tri_prep_kernel<<<256, 256>>>(tri);
    // one CTA per head: 1024 CTAs, 256 threads (8 warps x 32 query rows)
    TFA_88089779241014_kernel<<<1024, 256, SMEM_TOTAL>>>(q, k, v, mask, out);
}